// round 15
// baseline (speedup 1.0000x reference)
#include <cuda_runtime.h>
#include <math.h>
#include <stdint.h>

// Problem constants (B=1)
#define Cc    4      // chunks
#define Hh    8      // heads
#define Ll    1024   // chunk length
#define Dd    64     // head dim
#define Tt    (Cc*Ll)
#define NQUAD 544    // quads: (d, e0) with e0 = (d&~3)+4j
#define NSLOT 2176   // NQUAD*4 slots (invalid e<d slots have multiplier 0)
#define NVP   68     // padded row: 64 v + Z at col 64 + 3 pad
#define SCALEF 0.125f
#define EPSF   1e-6f

// ---------------- scratch (device globals; no allocation allowed) -----------
__device__ float g_g   [Cc*Hh*Ll];
__device__ float g_w   [Cc*Hh*Ll];
__device__ float g_qd  [Cc*Hh*Ll];
__device__ float g_gtot[Cc*Hh];
__device__ float g_P   [Cc*Hh*NSLOT*NVP];
__device__ float g_S   [Cc*Hh*NSLOT*NVP];
__device__ float g_intra[Tt*Hh*Dd];
__device__ float g_row  [Tt*Hh];
__device__ int   g_qd8 [NQUAD];     // quad -> d
__device__ int   g_qe0 [NQUAD];     // quad -> e0
__device__ float g_msl [NSLOT];     // slot multiplier: 0 (e<d), 1 (e==d), 2 (e>d)

// ---------------- mma.sync tf32 helper (baseline PTX, works on sm_103) -------
__device__ __forceinline__ void mma_tf32(float* c, const uint32_t* a,
                                         uint32_t b0, uint32_t b1) {
    asm volatile(
        "mma.sync.aligned.m16n8k8.row.col.f32.tf32.tf32.f32 "
        "{%0,%1,%2,%3}, {%4,%5,%6,%7}, {%8,%9}, {%0,%1,%2,%3};"
        : "+f"(c[0]), "+f"(c[1]), "+f"(c[2]), "+f"(c[3])
        : "r"(a[0]), "r"(a[1]), "r"(a[2]), "r"(a[3]), "r"(b0), "r"(b1));
}

// ---------------- K0: quad tables ---------------------------------------------
__global__ void k_pairs() {
    int qq = blockIdx.x * blockDim.x + threadIdx.x;
    if (qq >= NQUAD) return;
    int d = 0, base = 0;
    for (;;) {
        int cnt = 16 - (d >> 2);
        if (qq < base + cnt) break;
        base += cnt; d++;
    }
    int j = qq - base;
    int e0 = (d & ~3) + 4 * j;
    g_qd8[qq] = d;
    g_qe0[qq] = e0;
#pragma unroll
    for (int s = 0; s < 4; s++) {
        int e = e0 + s;
        g_msl[qq * 4 + s] = (e < d) ? 0.f : ((e == d) ? 1.f : 2.f);
    }
}

// ---------------- K1: gating cumsum + derived weights ------------------------
__global__ void k_gate(const float* __restrict__ logg) {
    int ch = blockIdx.x;
    int c = ch / Hh, h = ch % Hh;
    int l = threadIdx.x;
    __shared__ float sbuf[Ll];
    int t = c * Ll + l;
    sbuf[l] = logg[t * Hh + h];
    __syncthreads();
    for (int off = 1; off < Ll; off <<= 1) {
        float v   = sbuf[l];
        float add = (l >= off) ? sbuf[l - off] : 0.f;
        __syncthreads();
        sbuf[l] = v + add;
        __syncthreads();
    }
    float g    = sbuf[l];
    float gend = sbuf[Ll - 1];
    int idx = ch * Ll + l;
    g_g [idx] = g;
    g_w [idx] = expf(gend - g);
    g_qd[idx] = expf(g);
    if (l == 0) g_gtot[ch] = expf(gend);
}

// ---------------- K2: intra-chunk causal attention (scalar, unchanged) -------
__global__ void __launch_bounds__(128)
k_intra(const float* __restrict__ q, const float* __restrict__ k,
        const float* __restrict__ v) {
    int tl = 7 - blockIdx.x;
    int h = blockIdx.y, c = blockIdx.z;
    int lrow  = tl * 128 + threadIdx.x;
    int tglob = c * Ll + lrow;

    float qreg[Dd];
#pragma unroll
    for (int d = 0; d < Dd; d++)
        qreg[d] = q[(tglob * Hh + h) * Dd + d] * SCALEF;
    float gl = g_g[(c * Hh + h) * Ll + lrow];

    float acc[Dd];
#pragma unroll
    for (int d = 0; d < Dd; d++) acc[d] = 0.f;
    float rowsum = 0.f;

    __shared__ __align__(16) float Ks[64][68];
    __shared__ __align__(16) float Vs[64][68];
    __shared__ float Gs[64];

    int ntile = (tl + 1) * 2;
    for (int st = 0; st < ntile; st++) {
        int sbase = st * 64;
        __syncthreads();
        for (int idx = threadIdx.x; idx < 64 * Dd; idx += 128) {
            int r = idx >> 6, col = idx & 63;
            int ts = c * Ll + sbase + r;
            Ks[r][col] = k[(ts * Hh + h) * Dd + col];
            Vs[r][col] = v[(ts * Hh + h) * Dd + col];
        }
        if (threadIdx.x < 64)
            Gs[threadIdx.x] = g_g[(c * Hh + h) * Ll + sbase + threadIdx.x];
        __syncthreads();

        int smax = lrow - sbase + 1;
        if (smax > 64) smax = 64;
        for (int s = 0; s < smax; s++) {
            const float4* Kr = reinterpret_cast<const float4*>(&Ks[s][0]);
            float s0 = 0.f, s1 = 0.f, s2 = 0.f, s3 = 0.f;
#pragma unroll
            for (int d4 = 0; d4 < 16; d4++) {
                float4 kk = Kr[d4];
                s0 += qreg[4 * d4 + 0] * kk.x;
                s1 += qreg[4 * d4 + 1] * kk.y;
                s2 += qreg[4 * d4 + 2] * kk.z;
                s3 += qreg[4 * d4 + 3] * kk.w;
            }
            float sc = (s0 + s1) + (s2 + s3);
            float a  = __expf(gl - Gs[s]) * sc * sc;
            rowsum += a;
            const float4* Vr = reinterpret_cast<const float4*>(&Vs[s][0]);
#pragma unroll
            for (int d4 = 0; d4 < 16; d4++) {
                float4 vv = Vr[d4];
                acc[4 * d4 + 0] += a * vv.x;
                acc[4 * d4 + 1] += a * vv.y;
                acc[4 * d4 + 2] += a * vv.z;
                acc[4 * d4 + 3] += a * vv.w;
            }
        }
    }
    int ohid = tglob * Hh + h;
#pragma unroll
    for (int d = 0; d < Dd; d++) g_intra[ohid * Dd + d] = acc[d];
    g_row[ohid] = rowsum;
}

// ---------------- K3: state build via mma.sync tf32x3, N-split x2 ------------
// grid (17, Hh, Cc*2). split = z&1: split0 -> n-frags 0..4 (cols 0..39),
// split1 -> n-frags 4..8 (cols 32..71; writes only 40.., Z at 64).
__global__ void __launch_bounds__(128, 6)
k_state_mma(const float* __restrict__ k, const float* __restrict__ v) {
    __shared__ float  Kraw[32 * 65];
    __shared__ __align__(8) float2 Bt[32 * 41];   // (hi, lo) of staged B half

    int mt = blockIdx.x, h = blockIdx.y;
    int c = blockIdx.z >> 1, split = blockIdx.z & 1;
    int ch = c * Hh + h;
    int t = threadIdx.x;
    int w = t >> 5, lane = t & 31, gid = lane >> 2, tig = lane & 3;
    int cb = split * 32;                 // column base of this CTA's B half

    int dR[4], eR[4];
    float mR[4];
#pragma unroll
    for (int j = 0; j < 4; j++) {
        int slot = mt * 128 + w * 32 + gid + 8 * j;
        dR[j] = g_qd8[slot >> 2];
        eR[j] = g_qe0[slot >> 2] + (slot & 3);
        mR[j] = g_msl[slot];
    }

    float acc[40];
#pragma unroll
    for (int x = 0; x < 40; x++) acc[x] = 0.f;

    const float* wb = g_w + ch * Ll;

    for (int tile = 0; tile < 32; tile++) {
        int lb = tile * 32;
        __syncthreads();
        for (int idx = t; idx < 32 * 64; idx += 128) {
            int r = idx >> 6, col = idx & 63;
            Kraw[r * 65 + col] = k[((size_t)((c * Ll + lb + r) * Hh + h)) * Dd + col];
        }
        // stage this CTA's B half: cols cb..cb+39 of (V·w | w | 0)
        for (int idx = t; idx < 32 * 40; idx += 128) {
            int r = idx / 40, j = idx - r * 40;
            int col = cb + j;
            float wr = wb[lb + r];
            float val;
            if (col < 64)       val = v[((size_t)((c * Ll + lb + r) * Hh + h)) * Dd + col] * wr;
            else if (col == 64) val = wr;
            else                val = 0.f;
            uint32_t hb = __float_as_uint(val) & 0xFFFFE000u;
            float hf = __uint_as_float(hb);
            Bt[r * 41 + j] = make_float2(hf, val - hf);
        }
        __syncthreads();

#pragma unroll
        for (int ks = 0; ks < 4; ks++) {
            int l0 = ks * 8 + tig, l1 = l0 + 4;
            uint32_t ahi[2][4], alo[2][4];
#pragma unroll
            for (int j = 0; j < 4; j++) {
                float f0 = mR[j] * Kraw[l0 * 65 + dR[j]] * Kraw[l0 * 65 + eR[j]];
                float f1 = mR[j] * Kraw[l1 * 65 + dR[j]] * Kraw[l1 * 65 + eR[j]];
                uint32_t h0 = __float_as_uint(f0) & 0xFFFFE000u;
                uint32_t h1 = __float_as_uint(f1) & 0xFFFFE000u;
                int mf = j >> 1, rr = j & 1;
                ahi[mf][rr]     = h0;
                ahi[mf][rr + 2] = h1;
                alo[mf][rr]     = __float_as_uint(f0 - __uint_as_float(h0));
                alo[mf][rr + 2] = __float_as_uint(f1 - __uint_as_float(h1));
            }
#pragma unroll
            for (int nfi = 0; nfi < 5; nfi++) {
                float2 B0 = Bt[l0 * 41 + nfi * 8 + gid];
                float2 B1 = Bt[l1 * 41 + nfi * 8 + gid];
                uint32_t bh0 = __float_as_uint(B0.x), bl0 = __float_as_uint(B0.y);
                uint32_t bh1 = __float_as_uint(B1.x), bl1 = __float_as_uint(B1.y);
                float* c0 = acc + (0 * 5 + nfi) * 4;
                float* c1 = acc + (1 * 5 + nfi) * 4;
                mma_tf32(c0, ahi[0], bh0, bh1);
                mma_tf32(c1, ahi[1], bh0, bh1);
                mma_tf32(c0, ahi[0], bl0, bl1);
                mma_tf32(c1, ahi[1], bl0, bl1);
                mma_tf32(c0, alo[0], bh0, bh1);
                mma_tf32(c1, alo[1], bh0, bh1);
            }
        }
    }

    // epilogue: split0 writes cols 0..39; split1 writes cols 40..64 (skip nfi==0)
#pragma unroll
    for (int j = 0; j < 4; j++) {
        int slot = mt * 128 + w * 32 + gid + 8 * j;
        size_t base = ((size_t)ch * NSLOT + slot) * NVP;
        int mf = j >> 1, rr = j & 1;
#pragma unroll
        for (int nfi = 0; nfi < 5; nfi++) {
            if (split == 1 && nfi == 0) continue;   // overlap frag, owned by split0
            int col = cb + nfi * 8 + tig * 2;
            float v0 = acc[(mf * 5 + nfi) * 4 + rr * 2];
            float v1 = acc[(mf * 5 + nfi) * 4 + rr * 2 + 1];
            if (col < 64)
                *reinterpret_cast<float2*>(&g_P[base + col]) = make_float2(v0, v1);
            else if (col == 64)
                g_P[base + 64] = v0;
        }
    }
}

// ---------------- K4: pure prefix scan over chunks ---------------------------
__global__ void k_scan() {
    int idx = blockIdx.x * blockDim.x + threadIdx.x;
    const int per_h = NSLOT * NVP;
    const int tot = Hh * per_h;
    if (idx >= tot) return;
    int h = idx / per_h;
    int rem = idx % per_h;
    float s = 0.f;
    for (int c = 0; c < Cc; c++) {
        size_t off = (size_t)(c * Hh + h) * per_h + rem;
        g_S[off] = s;
        s = g_gtot[c * Hh + h] * s + g_P[off];
    }
}

// ---------------- K5: inter-chunk GEMM via mma.sync tf32x3, N-split x2 -------
// grid (8, Hh, Cc*2). split0 -> n-frags {0,1,2,3,8} (out cols 0..31 + Z),
// split1 -> n-frags {4,5,6,7,8} (out cols 32..63 + Z). Both compute Z (nfi==4).
__global__ void __launch_bounds__(128, 4)
k_inter_mma(const float* __restrict__ q, float* __restrict__ out) {
    __shared__ float Qs[128 * 65];
    __shared__ __align__(8) float2 Bs[32 * 41];
    __shared__ int sDs[32], sEs[32];

    int tl = blockIdx.x, h = blockIdx.y;
    int c = blockIdx.z >> 1, split = blockIdx.z & 1;
    int ch = c * Hh + h;
    int t = threadIdx.x;
    int w = t >> 5, lane = t & 31, gid = lane >> 2, tig = lane & 3;
    int cb = split * 32;                 // out-column base for nfi 0..3

    for (int idx = t; idx < 128 * 64; idx += 128) {
        int r = idx >> 6, col = idx & 63;
        int tg = c * Ll + tl * 128 + r;
        Qs[r * 65 + col] = q[((size_t)(tg * Hh + h)) * Dd + col] * SCALEF;
    }
    __syncthreads();

    float acc[40];
#pragma unroll
    for (int x = 0; x < 40; x++) acc[x] = 0.f;

    int Rrow[4];
#pragma unroll
    for (int j = 0; j < 4; j++) Rrow[j] = w * 32 + gid + 8 * j;

    if (c > 0) {
        const float* Sbase = &g_S[(size_t)ch * NSLOT * NVP];
        for (int kb = 0; kb < NSLOT; kb += 32) {
            __syncthreads();
            // stage B: cols (cb..cb+31) for nfi 0..3, cols 64..71 for nfi 4 (Z)
            for (int idx = t; idx < 32 * 40; idx += 128) {
                int r = idx / 40, j = idx - r * 40;
                int col = (j < 32) ? (cb + j) : (64 + (j - 32));
                float val = (col <= 64) ? Sbase[(size_t)(kb + r) * NVP + col] : 0.f;
                uint32_t hb = __float_as_uint(val) & 0xFFFFE000u;
                float hf = __uint_as_float(hb);
                Bs[r * 41 + j] = make_float2(hf, val - hf);
            }
            if (t < 32) {
                int s = kb + t;
                sDs[t] = g_qd8[s >> 2];
                sEs[t] = g_qe0[s >> 2] + (s & 3);
            }
            __syncthreads();

#pragma unroll
            for (int ks = 0; ks < 4; ks++) {
                int ls0 = ks * 8 + tig, ls1 = ls0 + 4;
                int d0 = sDs[ls0], e0 = sEs[ls0];
                int d1 = sDs[ls1], e1 = sEs[ls1];
                uint32_t ahi[2][4], alo[2][4];
#pragma unroll
                for (int j = 0; j < 4; j++) {
                    const float* qr = &Qs[Rrow[j] * 65];
                    float f0 = qr[d0] * qr[e0];
                    float f1 = qr[d1] * qr[e1];
                    uint32_t h0 = __float_as_uint(f0) & 0xFFFFE000u;
                    uint32_t h1 = __float_as_uint(f1) & 0xFFFFE000u;
                    int mf = j >> 1, rr = j & 1;
                    ahi[mf][rr]     = h0;
                    ahi[mf][rr + 2] = h1;
                    alo[mf][rr]     = __float_as_uint(f0 - __uint_as_float(h0));
                    alo[mf][rr + 2] = __float_as_uint(f1 - __uint_as_float(h1));
                }
#pragma unroll
                for (int nfi = 0; nfi < 5; nfi++) {
                    float2 B0 = Bs[ls0 * 41 + nfi * 8 + gid];
                    float2 B1 = Bs[ls1 * 41 + nfi * 8 + gid];
                    uint32_t bh0 = __float_as_uint(B0.x), bl0 = __float_as_uint(B0.y);
                    uint32_t bh1 = __float_as_uint(B1.x), bl1 = __float_as_uint(B1.y);
                    float* c0 = acc + (0 * 5 + nfi) * 4;
                    float* c1 = acc + (1 * 5 + nfi) * 4;
                    mma_tf32(c0, ahi[0], bh0, bh1);
                    mma_tf32(c1, ahi[1], bh0, bh1);
                    mma_tf32(c0, ahi[0], bl0, bl1);
                    mma_tf32(c1, ahi[1], bl0, bl1);
                    mma_tf32(c0, alo[0], bh0, bh1);
                    mma_tf32(c1, alo[1], bh0, bh1);
                }
            }
        }
    }

    // epilogue: den from Z frag (nfi==4, col 64 lives on tig==0), combine
    float invj[4], qdj[4];
#pragma unroll
    for (int j = 0; j < 4; j++) {
        int rl = tl * 128 + Rrow[j];
        qdj[j] = g_qd[ch * Ll + rl];
        float Z = acc[((j >> 1) * 5 + 4) * 4 + (j & 1) * 2];
        float den = g_row[(c * Ll + rl) * Hh + h] + qdj[j] * Z;
        float inv = 1.f / fmaxf(den, EPSF);
        invj[j] = __shfl_sync(0xffffffffu, inv, lane & ~3, 32);
    }
#pragma unroll
    for (int j = 0; j < 4; j++) {
        int rl = tl * 128 + Rrow[j];
        int ohid = (c * Ll + rl) * Hh + h;
        int mf = j >> 1, rr = j & 1;
#pragma unroll
        for (int nfi = 0; nfi < 4; nfi++) {
            int col = cb + nfi * 8 + tig * 2;
            float a0 = acc[(mf * 5 + nfi) * 4 + rr * 2];
            float a1 = acc[(mf * 5 + nfi) * 4 + rr * 2 + 1];
            float2 iv = *reinterpret_cast<const float2*>(&g_intra[(size_t)ohid * Dd + col]);
            float2 o;
            o.x = (iv.x + qdj[j] * a0) * invj[j];
            o.y = (iv.y + qdj[j] * a1) * invj[j];
            *reinterpret_cast<float2*>(&out[(size_t)ohid * Dd + col]) = o;
        }
    }
}

// ---------------- host launch -------------------------------------------------
extern "C" void kernel_launch(void* const* d_in, const int* in_sizes, int n_in,
                              void* d_out, int out_size) {
    const float* q  = (const float*)d_in[0];
    const float* k  = (const float*)d_in[1];
    const float* v  = (const float*)d_in[2];
    const float* lg = (const float*)d_in[3];
    float* out = (float*)d_out;

    k_pairs<<<(NQUAD + 127) / 128, 128>>>();
    k_gate <<<Cc * Hh, Ll>>>(lg);
    k_intra<<<dim3(8, Hh, Cc), 128>>>(q, k, v);
    k_state_mma<<<dim3(NSLOT / 128, Hh, Cc * 2), 128>>>(k, v);
    k_scan <<<(Hh * NSLOT * NVP + 255) / 256, 256>>>();
    k_inter_mma<<<dim3(8, Hh, Cc * 2), 128>>>(q, out);
}

// round 16
// speedup vs baseline: 1.0435x; 1.0435x over previous
#include <cuda_runtime.h>
#include <math.h>
#include <stdint.h>

// Problem constants (B=1)
#define Cc    4      // chunks
#define Hh    8      // heads
#define Ll    1024   // chunk length
#define Dd    64     // head dim
#define Tt    (Cc*Ll)
#define NQUAD 544    // quads: (d, e0) with e0 = (d&~3)+4j
#define NSLOT 2176   // NQUAD*4 slots (invalid e<d slots have multiplier 0)
#define NVP   68     // padded row: 64 v + Z at col 64 + 3 pad
#define SCALEF 0.125f
#define EPSF   1e-6f

// ---------------- scratch (device globals; no allocation allowed) -----------
__device__ float g_g   [Cc*Hh*Ll];
__device__ float g_w   [Cc*Hh*Ll];
__device__ float g_qd  [Cc*Hh*Ll];
__device__ float g_gtot[Cc*Hh];
__device__ float g_P   [Cc*Hh*NSLOT*NVP];
__device__ float g_S   [Cc*Hh*NSLOT*NVP];
__device__ float g_intra[Tt*Hh*Dd];
__device__ float g_row  [Tt*Hh];
__device__ int   g_qd8 [NQUAD];     // quad -> d
__device__ int   g_qe0 [NQUAD];     // quad -> e0
__device__ float g_msl [NSLOT];     // slot multiplier: 0 (e<d), 1 (e==d), 2 (e>d)

// ---------------- mma.sync tf32 helper (baseline PTX, works on sm_103) -------
__device__ __forceinline__ void mma_tf32(float* c, const uint32_t* a,
                                         uint32_t b0, uint32_t b1) {
    asm volatile(
        "mma.sync.aligned.m16n8k8.row.col.f32.tf32.tf32.f32 "
        "{%0,%1,%2,%3}, {%4,%5,%6,%7}, {%8,%9}, {%0,%1,%2,%3};"
        : "+f"(c[0]), "+f"(c[1]), "+f"(c[2]), "+f"(c[3])
        : "r"(a[0]), "r"(a[1]), "r"(a[2]), "r"(a[3]), "r"(b0), "r"(b1));
}

// ---------------- K0: quad tables ---------------------------------------------
__global__ void k_pairs() {
    int qq = blockIdx.x * blockDim.x + threadIdx.x;
    if (qq >= NQUAD) return;
    int d = 0, base = 0;
    for (;;) {
        int cnt = 16 - (d >> 2);
        if (qq < base + cnt) break;
        base += cnt; d++;
    }
    int j = qq - base;
    int e0 = (d & ~3) + 4 * j;
    g_qd8[qq] = d;
    g_qe0[qq] = e0;
#pragma unroll
    for (int s = 0; s < 4; s++) {
        int e = e0 + s;
        g_msl[qq * 4 + s] = (e < d) ? 0.f : ((e == d) ? 1.f : 2.f);
    }
}

// ---------------- K1: gating cumsum + derived weights ------------------------
__global__ void k_gate(const float* __restrict__ logg) {
    int ch = blockIdx.x;
    int c = ch / Hh, h = ch % Hh;
    int l = threadIdx.x;
    __shared__ float sbuf[Ll];
    int t = c * Ll + l;
    sbuf[l] = logg[t * Hh + h];
    __syncthreads();
    for (int off = 1; off < Ll; off <<= 1) {
        float v   = sbuf[l];
        float add = (l >= off) ? sbuf[l - off] : 0.f;
        __syncthreads();
        sbuf[l] = v + add;
        __syncthreads();
    }
    float g    = sbuf[l];
    float gend = sbuf[Ll - 1];
    int idx = ch * Ll + l;
    g_g [idx] = g;
    g_w [idx] = expf(gend - g);
    g_qd[idx] = expf(g);
    if (l == 0) g_gtot[ch] = expf(gend);
}

// ---------------- K2: intra-chunk causal attention (scalar, unchanged) -------
__global__ void __launch_bounds__(128)
k_intra(const float* __restrict__ q, const float* __restrict__ k,
        const float* __restrict__ v) {
    int tl = 7 - blockIdx.x;
    int h = blockIdx.y, c = blockIdx.z;
    int lrow  = tl * 128 + threadIdx.x;
    int tglob = c * Ll + lrow;

    float qreg[Dd];
#pragma unroll
    for (int d = 0; d < Dd; d++)
        qreg[d] = q[(tglob * Hh + h) * Dd + d] * SCALEF;
    float gl = g_g[(c * Hh + h) * Ll + lrow];

    float acc[Dd];
#pragma unroll
    for (int d = 0; d < Dd; d++) acc[d] = 0.f;
    float rowsum = 0.f;

    __shared__ __align__(16) float Ks[64][68];
    __shared__ __align__(16) float Vs[64][68];
    __shared__ float Gs[64];

    int ntile = (tl + 1) * 2;
    for (int st = 0; st < ntile; st++) {
        int sbase = st * 64;
        __syncthreads();
        for (int idx = threadIdx.x; idx < 64 * Dd; idx += 128) {
            int r = idx >> 6, col = idx & 63;
            int ts = c * Ll + sbase + r;
            Ks[r][col] = k[(ts * Hh + h) * Dd + col];
            Vs[r][col] = v[(ts * Hh + h) * Dd + col];
        }
        if (threadIdx.x < 64)
            Gs[threadIdx.x] = g_g[(c * Hh + h) * Ll + sbase + threadIdx.x];
        __syncthreads();

        int smax = lrow - sbase + 1;
        if (smax > 64) smax = 64;
        for (int s = 0; s < smax; s++) {
            const float4* Kr = reinterpret_cast<const float4*>(&Ks[s][0]);
            float s0 = 0.f, s1 = 0.f, s2 = 0.f, s3 = 0.f;
#pragma unroll
            for (int d4 = 0; d4 < 16; d4++) {
                float4 kk = Kr[d4];
                s0 += qreg[4 * d4 + 0] * kk.x;
                s1 += qreg[4 * d4 + 1] * kk.y;
                s2 += qreg[4 * d4 + 2] * kk.z;
                s3 += qreg[4 * d4 + 3] * kk.w;
            }
            float sc = (s0 + s1) + (s2 + s3);
            float a  = __expf(gl - Gs[s]) * sc * sc;
            rowsum += a;
            const float4* Vr = reinterpret_cast<const float4*>(&Vs[s][0]);
#pragma unroll
            for (int d4 = 0; d4 < 16; d4++) {
                float4 vv = Vr[d4];
                acc[4 * d4 + 0] += a * vv.x;
                acc[4 * d4 + 1] += a * vv.y;
                acc[4 * d4 + 2] += a * vv.z;
                acc[4 * d4 + 3] += a * vv.w;
            }
        }
    }
    int ohid = tglob * Hh + h;
#pragma unroll
    for (int d = 0; d < Dd; d++) g_intra[ohid * Dd + d] = acc[d];
    g_row[ohid] = rowsum;
}

// ---------------- K3: state build via mma.sync tf32x3 (full N, grouped) ------
// Per CTA: M=128 slots, N=72, K=1024. Grouped MMA issue: 3 nf per group,
// all hi*hi then hi*lo then lo*hi -> dep distance 6 (same per-acc FP order).
__global__ void __launch_bounds__(128)
k_state_mma(const float* __restrict__ k, const float* __restrict__ v) {
    __shared__ float  Kraw[32 * 65];
    __shared__ __align__(8) float2 Bt[32 * 73];   // (hi, lo) of (V·w | w | 0)

    int mt = blockIdx.x, h = blockIdx.y, c = blockIdx.z;
    int ch = c * Hh + h;
    int t = threadIdx.x;
    int w = t >> 5, lane = t & 31, gid = lane >> 2, tig = lane & 3;

    int dR[4], eR[4];
    float mR[4];
#pragma unroll
    for (int j = 0; j < 4; j++) {
        int slot = mt * 128 + w * 32 + gid + 8 * j;
        dR[j] = g_qd8[slot >> 2];
        eR[j] = g_qe0[slot >> 2] + (slot & 3);
        mR[j] = g_msl[slot];
    }

    float acc[72];
#pragma unroll
    for (int x = 0; x < 72; x++) acc[x] = 0.f;

    const float* wb = g_w + ch * Ll;

    for (int tile = 0; tile < 32; tile++) {
        int lb = tile * 32;
        __syncthreads();
        for (int idx = t; idx < 32 * 64; idx += 128) {
            int r = idx >> 6, col = idx & 63;
            Kraw[r * 65 + col] = k[((size_t)((c * Ll + lb + r) * Hh + h)) * Dd + col];
        }
        for (int idx = t; idx < 32 * 72; idx += 128) {
            int r = idx / 72, col = idx - r * 72;
            float wr = wb[lb + r];
            float val;
            if (col < 64)       val = v[((size_t)((c * Ll + lb + r) * Hh + h)) * Dd + col] * wr;
            else if (col == 64) val = wr;
            else                val = 0.f;
            uint32_t hb = __float_as_uint(val) & 0xFFFFE000u;
            float hf = __uint_as_float(hb);
            Bt[r * 73 + col] = make_float2(hf, val - hf);
        }
        __syncthreads();

#pragma unroll
        for (int ks = 0; ks < 4; ks++) {
            int l0 = ks * 8 + tig, l1 = l0 + 4;
            uint32_t ahi[2][4], alo[2][4];
#pragma unroll
            for (int j = 0; j < 4; j++) {
                float f0 = mR[j] * Kraw[l0 * 65 + dR[j]] * Kraw[l0 * 65 + eR[j]];
                float f1 = mR[j] * Kraw[l1 * 65 + dR[j]] * Kraw[l1 * 65 + eR[j]];
                uint32_t h0 = __float_as_uint(f0) & 0xFFFFE000u;
                uint32_t h1 = __float_as_uint(f1) & 0xFFFFE000u;
                int mf = j >> 1, rr = j & 1;
                ahi[mf][rr]     = h0;
                ahi[mf][rr + 2] = h1;
                alo[mf][rr]     = __float_as_uint(f0 - __uint_as_float(h0));
                alo[mf][rr + 2] = __float_as_uint(f1 - __uint_as_float(h1));
            }
#pragma unroll
            for (int g = 0; g < 3; g++) {
                uint32_t bh0[3], bh1[3], bl0[3], bl1[3];
#pragma unroll
                for (int i = 0; i < 3; i++) {
                    int nf = g * 3 + i;
                    float2 B0 = Bt[l0 * 73 + nf * 8 + gid];
                    float2 B1 = Bt[l1 * 73 + nf * 8 + gid];
                    bh0[i] = __float_as_uint(B0.x); bl0[i] = __float_as_uint(B0.y);
                    bh1[i] = __float_as_uint(B1.x); bl1[i] = __float_as_uint(B1.y);
                }
#pragma unroll
                for (int i = 0; i < 3; i++) {
                    mma_tf32(acc + (0 * 9 + g * 3 + i) * 4, ahi[0], bh0[i], bh1[i]);
                    mma_tf32(acc + (1 * 9 + g * 3 + i) * 4, ahi[1], bh0[i], bh1[i]);
                }
#pragma unroll
                for (int i = 0; i < 3; i++) {
                    mma_tf32(acc + (0 * 9 + g * 3 + i) * 4, ahi[0], bl0[i], bl1[i]);
                    mma_tf32(acc + (1 * 9 + g * 3 + i) * 4, ahi[1], bl0[i], bl1[i]);
                }
#pragma unroll
                for (int i = 0; i < 3; i++) {
                    mma_tf32(acc + (0 * 9 + g * 3 + i) * 4, alo[0], bh0[i], bh1[i]);
                    mma_tf32(acc + (1 * 9 + g * 3 + i) * 4, alo[1], bh0[i], bh1[i]);
                }
            }
        }
    }

    // epilogue: D[row][col] -> g_P
#pragma unroll
    for (int j = 0; j < 4; j++) {
        int slot = mt * 128 + w * 32 + gid + 8 * j;
        size_t base = ((size_t)ch * NSLOT + slot) * NVP;
        int mf = j >> 1, rr = j & 1;
#pragma unroll
        for (int nf = 0; nf < 9; nf++) {
            int col = nf * 8 + tig * 2;
            float v0 = acc[(mf * 9 + nf) * 4 + rr * 2];
            float v1 = acc[(mf * 9 + nf) * 4 + rr * 2 + 1];
            if (col < 64)
                *reinterpret_cast<float2*>(&g_P[base + col]) = make_float2(v0, v1);
            else if (col == 64)
                g_P[base + 64] = v0;
        }
    }
}

// ---------------- K4: pure prefix scan over chunks ---------------------------
__global__ void k_scan() {
    int idx = blockIdx.x * blockDim.x + threadIdx.x;
    const int per_h = NSLOT * NVP;
    const int tot = Hh * per_h;
    if (idx >= tot) return;
    int h = idx / per_h;
    int rem = idx % per_h;
    float s = 0.f;
    for (int c = 0; c < Cc; c++) {
        size_t off = (size_t)(c * Hh + h) * per_h + rem;
        g_S[off] = s;
        s = g_gtot[c * Hh + h] * s + g_P[off];
    }
}

// ---------------- K5: inter-chunk GEMM, M=64 rows/CTA, all-9-nf grouping -----
// grid (16, Hh, Cc). Warp w owns rows w*16..w*16+15 (1 m-frag). acc = 36 regs.
__global__ void __launch_bounds__(128)
k_inter_mma(const float* __restrict__ q, float* __restrict__ out) {
    __shared__ float Qs[64 * 65];
    __shared__ __align__(8) float2 Bs[32 * 73];
    __shared__ int sDs[32], sEs[32];

    int tl = blockIdx.x, h = blockIdx.y, c = blockIdx.z;
    int ch = c * Hh + h;
    int t = threadIdx.x;
    int w = t >> 5, lane = t & 31, gid = lane >> 2, tig = lane & 3;

    for (int idx = t; idx < 64 * 64; idx += 128) {
        int r = idx >> 6, col = idx & 63;
        int tg = c * Ll + tl * 64 + r;
        Qs[r * 65 + col] = q[((size_t)(tg * Hh + h)) * Dd + col] * SCALEF;
    }
    __syncthreads();

    float acc[36];
#pragma unroll
    for (int x = 0; x < 36; x++) acc[x] = 0.f;

    int row0 = w * 16 + gid;
    int row1 = row0 + 8;

    if (c > 0) {
        const float* Sbase = &g_S[(size_t)ch * NSLOT * NVP];
        for (int kb = 0; kb < NSLOT; kb += 32) {
            __syncthreads();
            for (int idx = t; idx < 32 * 72; idx += 128) {
                int r = idx / 72, col = idx - r * 72;
                float val = (col <= 64) ? Sbase[(size_t)(kb + r) * NVP + col] : 0.f;
                uint32_t hb = __float_as_uint(val) & 0xFFFFE000u;
                float hf = __uint_as_float(hb);
                Bs[r * 73 + col] = make_float2(hf, val - hf);
            }
            if (t < 32) {
                int s = kb + t;
                sDs[t] = g_qd8[s >> 2];
                sEs[t] = g_qe0[s >> 2] + (s & 3);
            }
            __syncthreads();

#pragma unroll
            for (int ks = 0; ks < 4; ks++) {
                int ls0 = ks * 8 + tig, ls1 = ls0 + 4;
                int d0 = sDs[ls0], e0 = sEs[ls0];
                int d1 = sDs[ls1], e1 = sEs[ls1];
                const float* qr0 = &Qs[row0 * 65];
                const float* qr1 = &Qs[row1 * 65];
                float f0 = qr0[d0] * qr0[e0];
                float f1 = qr1[d0] * qr1[e0];
                float f2 = qr0[d1] * qr0[e1];
                float f3 = qr1[d1] * qr1[e1];
                uint32_t ahi[4], alo[4];
                uint32_t h0 = __float_as_uint(f0) & 0xFFFFE000u;
                uint32_t h1 = __float_as_uint(f1) & 0xFFFFE000u;
                uint32_t h2 = __float_as_uint(f2) & 0xFFFFE000u;
                uint32_t h3 = __float_as_uint(f3) & 0xFFFFE000u;
                ahi[0] = h0; ahi[1] = h1; ahi[2] = h2; ahi[3] = h3;
                alo[0] = __float_as_uint(f0 - __uint_as_float(h0));
                alo[1] = __float_as_uint(f1 - __uint_as_float(h1));
                alo[2] = __float_as_uint(f2 - __uint_as_float(h2));
                alo[3] = __float_as_uint(f3 - __uint_as_float(h3));

                uint32_t bh0[9], bh1[9], bl0[9], bl1[9];
#pragma unroll
                for (int nf = 0; nf < 9; nf++) {
                    float2 B0 = Bs[ls0 * 73 + nf * 8 + gid];
                    float2 B1 = Bs[ls1 * 73 + nf * 8 + gid];
                    bh0[nf] = __float_as_uint(B0.x); bl0[nf] = __float_as_uint(B0.y);
                    bh1[nf] = __float_as_uint(B1.x); bl1[nf] = __float_as_uint(B1.y);
                }
#pragma unroll
                for (int nf = 0; nf < 9; nf++)
                    mma_tf32(acc + nf * 4, ahi, bh0[nf], bh1[nf]);
#pragma unroll
                for (int nf = 0; nf < 9; nf++)
                    mma_tf32(acc + nf * 4, ahi, bl0[nf], bl1[nf]);
#pragma unroll
                for (int nf = 0; nf < 9; nf++)
                    mma_tf32(acc + nf * 4, alo, bh0[nf], bh1[nf]);
            }
        }
    }

    // epilogue: den from Z (nf==8 col 64, tig==0 lanes), combine with intra
    float invj[2], qdj[2];
#pragma unroll
    for (int j = 0; j < 2; j++) {
        int row = (j == 0) ? row0 : row1;
        int rl = tl * 64 + row;
        qdj[j] = g_qd[ch * Ll + rl];
        float Z = acc[8 * 4 + j * 2];
        float den = g_row[(c * Ll + rl) * Hh + h] + qdj[j] * Z;
        float inv = 1.f / fmaxf(den, EPSF);
        invj[j] = __shfl_sync(0xffffffffu, inv, lane & ~3, 32);
    }
#pragma unroll
    for (int j = 0; j < 2; j++) {
        int row = (j == 0) ? row0 : row1;
        int rl = tl * 64 + row;
        int ohid = (c * Ll + rl) * Hh + h;
#pragma unroll
        for (int nf = 0; nf < 8; nf++) {
            int col = nf * 8 + tig * 2;
            float a0 = acc[nf * 4 + j * 2];
            float a1 = acc[nf * 4 + j * 2 + 1];
            float2 iv = *reinterpret_cast<const float2*>(&g_intra[(size_t)ohid * Dd + col]);
            float2 o;
            o.x = (iv.x + qdj[j] * a0) * invj[j];
            o.y = (iv.y + qdj[j] * a1) * invj[j];
            *reinterpret_cast<float2*>(&out[(size_t)ohid * Dd + col]) = o;
        }
    }
}

// ---------------- host launch -------------------------------------------------
extern "C" void kernel_launch(void* const* d_in, const int* in_sizes, int n_in,
                              void* d_out, int out_size) {
    const float* q  = (const float*)d_in[0];
    const float* k  = (const float*)d_in[1];
    const float* v  = (const float*)d_in[2];
    const float* lg = (const float*)d_in[3];
    float* out = (float*)d_out;

    k_pairs<<<(NQUAD + 127) / 128, 128>>>();
    k_gate <<<Cc * Hh, Ll>>>(lg);
    k_intra<<<dim3(8, Hh, Cc), 128>>>(q, k, v);
    k_state_mma<<<dim3(NSLOT / 128, Hh, Cc), 128>>>(k, v);
    k_scan <<<(Hh * NSLOT * NVP + 255) / 256, 256>>>();
    k_inter_mma<<<dim3(16, Hh, Cc), 128>>>(q, out);
}

// round 17
// speedup vs baseline: 1.3237x; 1.2685x over previous
#include <cuda_runtime.h>
#include <math.h>
#include <stdint.h>

// Problem constants (B=1)
#define Cc    4      // chunks
#define Hh    8      // heads
#define Ll    1024   // chunk length
#define Dd    64     // head dim
#define Tt    (Cc*Ll)
#define NQUAD 544    // quads: (d, e0) with e0 = (d&~3)+4j
#define NSLOT 2176   // NQUAD*4 slots (invalid e<d slots have multiplier 0)
#define NVP   68     // padded row: 64 v + Z at col 64 + 3 pad
#define SCALEF 0.125f
#define EPSF   1e-6f

// ---------------- scratch (device globals; no allocation allowed) -----------
__device__ float g_g   [Cc*Hh*Ll];
__device__ float g_w   [Cc*Hh*Ll];
__device__ float g_qd  [Cc*Hh*Ll];
__device__ float g_gtot[Cc*Hh];
__device__ float g_P   [Cc*Hh*NSLOT*NVP];
__device__ float g_S   [Cc*Hh*NSLOT*NVP];
__device__ float g_intra[Tt*Hh*Dd];
__device__ float g_row  [Tt*Hh];
__device__ int   g_qd8 [NQUAD];     // quad -> d
__device__ int   g_qe0 [NQUAD];     // quad -> e0
__device__ float g_msl [NSLOT];     // slot multiplier: 0 (e<d), 1 (e==d), 2 (e>d)

// ---------------- mma.sync tf32 helper (baseline PTX, works on sm_103) -------
__device__ __forceinline__ void mma_tf32(float* c, const uint32_t* a,
                                         uint32_t b0, uint32_t b1) {
    asm volatile(
        "mma.sync.aligned.m16n8k8.row.col.f32.tf32.tf32.f32 "
        "{%0,%1,%2,%3}, {%4,%5,%6,%7}, {%8,%9}, {%0,%1,%2,%3};"
        : "+f"(c[0]), "+f"(c[1]), "+f"(c[2]), "+f"(c[3])
        : "r"(a[0]), "r"(a[1]), "r"(a[2]), "r"(a[3]), "r"(b0), "r"(b1));
}

// ---------------- K0: quad tables ---------------------------------------------
__global__ void k_pairs() {
    int qq = blockIdx.x * blockDim.x + threadIdx.x;
    if (qq >= NQUAD) return;
    int d = 0, base = 0;
    for (;;) {
        int cnt = 16 - (d >> 2);
        if (qq < base + cnt) break;
        base += cnt; d++;
    }
    int j = qq - base;
    int e0 = (d & ~3) + 4 * j;
    g_qd8[qq] = d;
    g_qe0[qq] = e0;
#pragma unroll
    for (int s = 0; s < 4; s++) {
        int e = e0 + s;
        g_msl[qq * 4 + s] = (e < d) ? 0.f : ((e == d) ? 1.f : 2.f);
    }
}

// ---------------- K1: gating cumsum + derived weights ------------------------
__global__ void k_gate(const float* __restrict__ logg) {
    int ch = blockIdx.x;
    int c = ch / Hh, h = ch % Hh;
    int l = threadIdx.x;
    __shared__ float sbuf[Ll];
    int t = c * Ll + l;
    sbuf[l] = logg[t * Hh + h];
    __syncthreads();
    for (int off = 1; off < Ll; off <<= 1) {
        float v   = sbuf[l];
        float add = (l >= off) ? sbuf[l - off] : 0.f;
        __syncthreads();
        sbuf[l] = v + add;
        __syncthreads();
    }
    float g    = sbuf[l];
    float gend = sbuf[Ll - 1];
    int idx = ch * Ll + l;
    g_g [idx] = g;
    g_w [idx] = expf(gend - g);
    g_qd[idx] = expf(g);
    if (l == 0) g_gtot[ch] = expf(gend);
}

// ---------------- K2: intra-chunk causal attention via mma.sync tf32x3 -------
// grid (16, Hh, Cc). M=64 q-rows/CTA, warp w owns rows w*16..w*16+15 (1 m-frag).
// Per 32-key tile: GEMM1 Q*K^T -> mask/exp/square on D-frags -> shfl permute
// to A-frags -> GEMM2 A*V. Rowsum accumulated from the a-values directly.
#define IN_QSTR 68
#define IN_KSTR 67
#define IN_QS   0
#define IN_KS   (64 * IN_QSTR * 4)                  // 17408
#define IN_VS   (IN_KS + 32 * IN_KSTR * 8)          // 34560
#define IN_GS   (IN_VS + 32 * IN_KSTR * 8)          // 51712
#define IN_SIZE (IN_GS + 32 * 4)                    // 51840

__global__ void __launch_bounds__(128)
k_intra_mma(const float* __restrict__ q, const float* __restrict__ k,
            const float* __restrict__ v) {
    extern __shared__ char ismem[];
    float*  Qs = reinterpret_cast<float*>(ismem + IN_QS);
    float2* Ks = reinterpret_cast<float2*>(ismem + IN_KS);
    float2* Vs = reinterpret_cast<float2*>(ismem + IN_VS);
    float*  Gs = reinterpret_cast<float*>(ismem + IN_GS);

    int tl = blockIdx.x, h = blockIdx.y, c = blockIdx.z;
    int ch = c * Hh + h;
    int t = threadIdx.x;
    int w = t >> 5, lane = t & 31, gid = lane >> 2, tig = lane & 3;
    int rbase = tl * 64;

    // stage Q (scaled), stride 68 -> conflict-free a-frag loads
    for (int idx = t; idx < 64 * 64; idx += 128) {
        int r = idx >> 6, col = idx & 63;
        Qs[r * IN_QSTR + col] =
            q[((size_t)((c * Ll + rbase + r) * Hh + h)) * Dd + col] * SCALEF;
    }

    int r0 = w * 16 + gid;            // CTA-local rows
    int r1 = r0 + 8;
    float gl0 = g_g[ch * Ll + rbase + r0];
    float gl1 = g_g[ch * Ll + rbase + r1];
    int wmax = rbase + w * 16 + 15;   // warp's max row (chunk-local)

    float accV[32];
#pragma unroll
    for (int x = 0; x < 32; x++) accV[x] = 0.f;
    float rs0 = 0.f, rs1 = 0.f;

    int ntile = 2 * (tl + 1);
    for (int kt = 0; kt < ntile; kt++) {
        int kb = kt * 32;
        __syncthreads();
        // stage K,V hi/lo split + G
        for (int idx = t; idx < 32 * 64; idx += 128) {
            int r = idx >> 6, col = idx & 63;
            size_t gix = ((size_t)((c * Ll + kb + r) * Hh + h)) * Dd + col;
            float kv = k[gix];
            uint32_t hb = __float_as_uint(kv) & 0xFFFFE000u;
            float hf = __uint_as_float(hb);
            Ks[r * IN_KSTR + col] = make_float2(hf, kv - hf);
            float vv = v[gix];
            uint32_t vb = __float_as_uint(vv) & 0xFFFFE000u;
            float vf = __uint_as_float(vb);
            Vs[r * IN_KSTR + col] = make_float2(vf, vv - vf);
        }
        if (t < 32) Gs[t] = g_g[ch * Ll + kb + t];
        __syncthreads();

        if (kb > wmax) continue;      // warp-uniform causal skip

        // ---- GEMM1: D1 = Q * K^T (tf32x3) ----
        float D1[16];
#pragma unroll
        for (int x = 0; x < 16; x++) D1[x] = 0.f;
#pragma unroll
        for (int ks = 0; ks < 8; ks++) {
            float q0 = Qs[r0 * IN_QSTR + ks * 8 + tig];
            float q1 = Qs[r1 * IN_QSTR + ks * 8 + tig];
            float q2 = Qs[r0 * IN_QSTR + ks * 8 + tig + 4];
            float q3 = Qs[r1 * IN_QSTR + ks * 8 + tig + 4];
            uint32_t ahi[4], alo[4];
            uint32_t h0 = __float_as_uint(q0) & 0xFFFFE000u;
            uint32_t h1 = __float_as_uint(q1) & 0xFFFFE000u;
            uint32_t h2 = __float_as_uint(q2) & 0xFFFFE000u;
            uint32_t h3 = __float_as_uint(q3) & 0xFFFFE000u;
            ahi[0] = h0; ahi[1] = h1; ahi[2] = h2; ahi[3] = h3;
            alo[0] = __float_as_uint(q0 - __uint_as_float(h0));
            alo[1] = __float_as_uint(q1 - __uint_as_float(h1));
            alo[2] = __float_as_uint(q2 - __uint_as_float(h2));
            alo[3] = __float_as_uint(q3 - __uint_as_float(h3));
#pragma unroll
            for (int nf = 0; nf < 4; nf++) {
                float2 B0 = Ks[(nf * 8 + gid) * IN_KSTR + ks * 8 + tig];
                float2 B1 = Ks[(nf * 8 + gid) * IN_KSTR + ks * 8 + tig + 4];
                uint32_t bh0 = __float_as_uint(B0.x), bl0 = __float_as_uint(B0.y);
                uint32_t bh1 = __float_as_uint(B1.x), bl1 = __float_as_uint(B1.y);
                mma_tf32(D1 + nf * 4, ahi, bh0, bh1);
                mma_tf32(D1 + nf * 4, ahi, bl0, bl1);
                mma_tf32(D1 + nf * 4, alo, bh0, bh1);
            }
        }

        // ---- elementwise: causal mask, exp, square; rowsum ----
        int l0g = rbase + r0, l1g = rbase + r1;
#pragma unroll
        for (int nf = 0; nf < 4; nf++) {
            int s0 = kb + nf * 8 + tig * 2;
            int s1 = s0 + 1;
            float gs0 = Gs[nf * 8 + tig * 2];
            float gs1 = Gs[nf * 8 + tig * 2 + 1];
            float sc, a;
            sc = D1[nf*4+0]; a = (s0 <= l0g) ? __expf(gl0 - gs0) * sc * sc : 0.f;
            D1[nf*4+0] = a; rs0 += a;
            sc = D1[nf*4+1]; a = (s1 <= l0g) ? __expf(gl0 - gs1) * sc * sc : 0.f;
            D1[nf*4+1] = a; rs0 += a;
            sc = D1[nf*4+2]; a = (s0 <= l1g) ? __expf(gl1 - gs0) * sc * sc : 0.f;
            D1[nf*4+2] = a; rs1 += a;
            sc = D1[nf*4+3]; a = (s1 <= l1g) ? __expf(gl1 - gs1) * sc * sc : 0.f;
            D1[nf*4+3] = a; rs1 += a;
        }

        // ---- GEMM2: accV += A * V (A from D1 via shfl permute) ----
#pragma unroll
        for (int kf = 0; kf < 4; kf++) {
            int Lb = (gid << 2) | (tig >> 1);
            int L2 = Lb + 2;
            float v0 = __shfl_sync(0xffffffffu, D1[kf*4+0], Lb, 32);
            float v1 = __shfl_sync(0xffffffffu, D1[kf*4+1], Lb, 32);
            float v2 = __shfl_sync(0xffffffffu, D1[kf*4+2], Lb, 32);
            float v3 = __shfl_sync(0xffffffffu, D1[kf*4+3], Lb, 32);
            float u0 = __shfl_sync(0xffffffffu, D1[kf*4+0], L2, 32);
            float u1 = __shfl_sync(0xffffffffu, D1[kf*4+1], L2, 32);
            float u2 = __shfl_sync(0xffffffffu, D1[kf*4+2], L2, 32);
            float u3 = __shfl_sync(0xffffffffu, D1[kf*4+3], L2, 32);
            bool odd = (tig & 1);
            float a0 = odd ? v1 : v0;     // (row gid,   k = kf*8+tig)
            float a1 = odd ? v3 : v2;     // (row gid+8, k = kf*8+tig)
            float a2 = odd ? u1 : u0;     // (row gid,   k = kf*8+tig+4)
            float a3 = odd ? u3 : u2;     // (row gid+8, k = kf*8+tig+4)
            uint32_t ahi[4], alo[4];
            uint32_t h0 = __float_as_uint(a0) & 0xFFFFE000u;
            uint32_t h1 = __float_as_uint(a1) & 0xFFFFE000u;
            uint32_t h2 = __float_as_uint(a2) & 0xFFFFE000u;
            uint32_t h3 = __float_as_uint(a3) & 0xFFFFE000u;
            ahi[0] = h0; ahi[1] = h1; ahi[2] = h2; ahi[3] = h3;
            alo[0] = __float_as_uint(a0 - __uint_as_float(h0));
            alo[1] = __float_as_uint(a1 - __uint_as_float(h1));
            alo[2] = __float_as_uint(a2 - __uint_as_float(h2));
            alo[3] = __float_as_uint(a3 - __uint_as_float(h3));
#pragma unroll
            for (int nf = 0; nf < 8; nf++) {
                float2 B0 = Vs[(kf * 8 + tig) * IN_KSTR + nf * 8 + gid];
                float2 B1 = Vs[(kf * 8 + tig + 4) * IN_KSTR + nf * 8 + gid];
                uint32_t bh0 = __float_as_uint(B0.x), bl0 = __float_as_uint(B0.y);
                uint32_t bh1 = __float_as_uint(B1.x), bl1 = __float_as_uint(B1.y);
                mma_tf32(accV + nf * 4, ahi, bh0, bh1);
                mma_tf32(accV + nf * 4, ahi, bl0, bl1);
                mma_tf32(accV + nf * 4, alo, bh0, bh1);
            }
        }
    }

    // rowsum reduce over the 4 lanes sharing gid
    rs0 += __shfl_xor_sync(0xffffffffu, rs0, 1, 32);
    rs0 += __shfl_xor_sync(0xffffffffu, rs0, 2, 32);
    rs1 += __shfl_xor_sync(0xffffffffu, rs1, 1, 32);
    rs1 += __shfl_xor_sync(0xffffffffu, rs1, 2, 32);
    int tg0 = c * Ll + rbase + r0;
    int tg1 = c * Ll + rbase + r1;
    if (tig == 0) {
        g_row[tg0 * Hh + h] = rs0;
        g_row[tg1 * Hh + h] = rs1;
    }
#pragma unroll
    for (int nf = 0; nf < 8; nf++) {
        int col = nf * 8 + tig * 2;
        *reinterpret_cast<float2*>(&g_intra[((size_t)(tg0 * Hh + h)) * Dd + col]) =
            make_float2(accV[nf*4+0], accV[nf*4+1]);
        *reinterpret_cast<float2*>(&g_intra[((size_t)(tg1 * Hh + h)) * Dd + col]) =
            make_float2(accV[nf*4+2], accV[nf*4+3]);
    }
}

// ---------------- K3: state build via mma.sync tf32x3 (rd14 known-good) ------
__global__ void __launch_bounds__(128)
k_state_mma(const float* __restrict__ k, const float* __restrict__ v) {
    __shared__ float  Kraw[32 * 65];
    __shared__ __align__(8) float2 Bt[32 * 73];   // (hi, lo) of (V·w | w | 0)

    int mt = blockIdx.x, h = blockIdx.y, c = blockIdx.z;
    int ch = c * Hh + h;
    int t = threadIdx.x;
    int w = t >> 5, lane = t & 31, gid = lane >> 2, tig = lane & 3;

    int dR[4], eR[4];
    float mR[4];
#pragma unroll
    for (int j = 0; j < 4; j++) {
        int slot = mt * 128 + w * 32 + gid + 8 * j;
        dR[j] = g_qd8[slot >> 2];
        eR[j] = g_qe0[slot >> 2] + (slot & 3);
        mR[j] = g_msl[slot];
    }

    float acc[72];
#pragma unroll
    for (int x = 0; x < 72; x++) acc[x] = 0.f;

    const float* wb = g_w + ch * Ll;

    for (int tile = 0; tile < 32; tile++) {
        int lb = tile * 32;
        __syncthreads();
        for (int idx = t; idx < 32 * 64; idx += 128) {
            int r = idx >> 6, col = idx & 63;
            Kraw[r * 65 + col] = k[((size_t)((c * Ll + lb + r) * Hh + h)) * Dd + col];
        }
        for (int idx = t; idx < 32 * 72; idx += 128) {
            int r = idx / 72, col = idx - r * 72;
            float wr = wb[lb + r];
            float val;
            if (col < 64)       val = v[((size_t)((c * Ll + lb + r) * Hh + h)) * Dd + col] * wr;
            else if (col == 64) val = wr;
            else                val = 0.f;
            uint32_t hb = __float_as_uint(val) & 0xFFFFE000u;
            float hf = __uint_as_float(hb);
            Bt[r * 73 + col] = make_float2(hf, val - hf);
        }
        __syncthreads();

#pragma unroll
        for (int ks = 0; ks < 4; ks++) {
            int l0 = ks * 8 + tig, l1 = l0 + 4;
            uint32_t ahi[2][4], alo[2][4];
#pragma unroll
            for (int j = 0; j < 4; j++) {
                float f0 = mR[j] * Kraw[l0 * 65 + dR[j]] * Kraw[l0 * 65 + eR[j]];
                float f1 = mR[j] * Kraw[l1 * 65 + dR[j]] * Kraw[l1 * 65 + eR[j]];
                uint32_t h0 = __float_as_uint(f0) & 0xFFFFE000u;
                uint32_t h1 = __float_as_uint(f1) & 0xFFFFE000u;
                int mf = j >> 1, rr = j & 1;
                ahi[mf][rr]     = h0;
                ahi[mf][rr + 2] = h1;
                alo[mf][rr]     = __float_as_uint(f0 - __uint_as_float(h0));
                alo[mf][rr + 2] = __float_as_uint(f1 - __uint_as_float(h1));
            }
#pragma unroll
            for (int nf = 0; nf < 9; nf++) {
                float2 B0 = Bt[l0 * 73 + nf * 8 + gid];
                float2 B1 = Bt[l1 * 73 + nf * 8 + gid];
                uint32_t bh0 = __float_as_uint(B0.x), bl0 = __float_as_uint(B0.y);
                uint32_t bh1 = __float_as_uint(B1.x), bl1 = __float_as_uint(B1.y);
#pragma unroll
                for (int mf = 0; mf < 2; mf++) {
                    float* cc = acc + (mf * 9 + nf) * 4;
                    mma_tf32(cc, ahi[mf], bh0, bh1);
                    mma_tf32(cc, ahi[mf], bl0, bl1);
                    mma_tf32(cc, alo[mf], bh0, bh1);
                }
            }
        }
    }

    // epilogue: D[row][col] -> g_P
#pragma unroll
    for (int j = 0; j < 4; j++) {
        int slot = mt * 128 + w * 32 + gid + 8 * j;
        size_t base = ((size_t)ch * NSLOT + slot) * NVP;
        int mf = j >> 1, rr = j & 1;
#pragma unroll
        for (int nf = 0; nf < 9; nf++) {
            int col = nf * 8 + tig * 2;
            float v0 = acc[(mf * 9 + nf) * 4 + rr * 2];
            float v1 = acc[(mf * 9 + nf) * 4 + rr * 2 + 1];
            if (col < 64)
                *reinterpret_cast<float2*>(&g_P[base + col]) = make_float2(v0, v1);
            else if (col == 64)
                g_P[base + 64] = v0;
        }
    }
}

// ---------------- K4: pure prefix scan over chunks ---------------------------
__global__ void k_scan() {
    int idx = blockIdx.x * blockDim.x + threadIdx.x;
    const int per_h = NSLOT * NVP;
    const int tot = Hh * per_h;
    if (idx >= tot) return;
    int h = idx / per_h;
    int rem = idx % per_h;
    float s = 0.f;
    for (int c = 0; c < Cc; c++) {
        size_t off = (size_t)(c * Hh + h) * per_h + rem;
        g_S[off] = s;
        s = g_gtot[c * Hh + h] * s + g_P[off];
    }
}

// ---------------- K5: inter-chunk GEMM, M=64 rows/CTA (rd16 form) ------------
__global__ void __launch_bounds__(128)
k_inter_mma(const float* __restrict__ q, float* __restrict__ out) {
    __shared__ float Qs[64 * 65];
    __shared__ __align__(8) float2 Bs[32 * 73];
    __shared__ int sDs[32], sEs[32];

    int tl = blockIdx.x, h = blockIdx.y, c = blockIdx.z;
    int ch = c * Hh + h;
    int t = threadIdx.x;
    int w = t >> 5, lane = t & 31, gid = lane >> 2, tig = lane & 3;

    for (int idx = t; idx < 64 * 64; idx += 128) {
        int r = idx >> 6, col = idx & 63;
        int tg = c * Ll + tl * 64 + r;
        Qs[r * 65 + col] = q[((size_t)(tg * Hh + h)) * Dd + col] * SCALEF;
    }
    __syncthreads();

    float acc[36];
#pragma unroll
    for (int x = 0; x < 36; x++) acc[x] = 0.f;

    int row0 = w * 16 + gid;
    int row1 = row0 + 8;

    if (c > 0) {
        const float* Sbase = &g_S[(size_t)ch * NSLOT * NVP];
        for (int kb = 0; kb < NSLOT; kb += 32) {
            __syncthreads();
            for (int idx = t; idx < 32 * 72; idx += 128) {
                int r = idx / 72, col = idx - r * 72;
                float val = (col <= 64) ? Sbase[(size_t)(kb + r) * NVP + col] : 0.f;
                uint32_t hb = __float_as_uint(val) & 0xFFFFE000u;
                float hf = __uint_as_float(hb);
                Bs[r * 73 + col] = make_float2(hf, val - hf);
            }
            if (t < 32) {
                int s = kb + t;
                sDs[t] = g_qd8[s >> 2];
                sEs[t] = g_qe0[s >> 2] + (s & 3);
            }
            __syncthreads();

#pragma unroll
            for (int ks = 0; ks < 4; ks++) {
                int ls0 = ks * 8 + tig, ls1 = ls0 + 4;
                int d0 = sDs[ls0], e0 = sEs[ls0];
                int d1 = sDs[ls1], e1 = sEs[ls1];
                const float* qr0 = &Qs[row0 * 65];
                const float* qr1 = &Qs[row1 * 65];
                float f0 = qr0[d0] * qr0[e0];
                float f1 = qr1[d0] * qr1[e0];
                float f2 = qr0[d1] * qr0[e1];
                float f3 = qr1[d1] * qr1[e1];
                uint32_t ahi[4], alo[4];
                uint32_t h0 = __float_as_uint(f0) & 0xFFFFE000u;
                uint32_t h1 = __float_as_uint(f1) & 0xFFFFE000u;
                uint32_t h2 = __float_as_uint(f2) & 0xFFFFE000u;
                uint32_t h3 = __float_as_uint(f3) & 0xFFFFE000u;
                ahi[0] = h0; ahi[1] = h1; ahi[2] = h2; ahi[3] = h3;
                alo[0] = __float_as_uint(f0 - __uint_as_float(h0));
                alo[1] = __float_as_uint(f1 - __uint_as_float(h1));
                alo[2] = __float_as_uint(f2 - __uint_as_float(h2));
                alo[3] = __float_as_uint(f3 - __uint_as_float(h3));

                uint32_t bh0[9], bh1[9], bl0[9], bl1[9];
#pragma unroll
                for (int nf = 0; nf < 9; nf++) {
                    float2 B0 = Bs[ls0 * 73 + nf * 8 + gid];
                    float2 B1 = Bs[ls1 * 73 + nf * 8 + gid];
                    bh0[nf] = __float_as_uint(B0.x); bl0[nf] = __float_as_uint(B0.y);
                    bh1[nf] = __float_as_uint(B1.x); bl1[nf] = __float_as_uint(B1.y);
                }
#pragma unroll
                for (int nf = 0; nf < 9; nf++)
                    mma_tf32(acc + nf * 4, ahi, bh0[nf], bh1[nf]);
#pragma unroll
                for (int nf = 0; nf < 9; nf++)
                    mma_tf32(acc + nf * 4, ahi, bl0[nf], bl1[nf]);
#pragma unroll
                for (int nf = 0; nf < 9; nf++)
                    mma_tf32(acc + nf * 4, alo, bh0[nf], bh1[nf]);
            }
        }
    }

    // epilogue: den from Z (nf==8 col 64, tig==0 lanes), combine with intra
    float invj[2], qdj[2];
#pragma unroll
    for (int j = 0; j < 2; j++) {
        int row = (j == 0) ? row0 : row1;
        int rl = tl * 64 + row;
        qdj[j] = g_qd[ch * Ll + rl];
        float Z = acc[8 * 4 + j * 2];
        float den = g_row[(c * Ll + rl) * Hh + h] + qdj[j] * Z;
        float inv = 1.f / fmaxf(den, EPSF);
        invj[j] = __shfl_sync(0xffffffffu, inv, lane & ~3, 32);
    }
#pragma unroll
    for (int j = 0; j < 2; j++) {
        int row = (j == 0) ? row0 : row1;
        int rl = tl * 64 + row;
        int ohid = (c * Ll + rl) * Hh + h;
#pragma unroll
        for (int nf = 0; nf < 8; nf++) {
            int col = nf * 8 + tig * 2;
            float a0 = acc[nf * 4 + j * 2];
            float a1 = acc[nf * 4 + j * 2 + 1];
            float2 iv = *reinterpret_cast<const float2*>(&g_intra[(size_t)ohid * Dd + col]);
            float2 o;
            o.x = (iv.x + qdj[j] * a0) * invj[j];
            o.y = (iv.y + qdj[j] * a1) * invj[j];
            *reinterpret_cast<float2*>(&out[(size_t)ohid * Dd + col]) = o;
        }
    }
}

// ---------------- host launch -------------------------------------------------
extern "C" void kernel_launch(void* const* d_in, const int* in_sizes, int n_in,
                              void* d_out, int out_size) {
    const float* q  = (const float*)d_in[0];
    const float* k  = (const float*)d_in[1];
    const float* v  = (const float*)d_in[2];
    const float* lg = (const float*)d_in[3];
    float* out = (float*)d_out;

    cudaFuncSetAttribute(k_intra_mma,
                         cudaFuncAttributeMaxDynamicSharedMemorySize, IN_SIZE);

    k_pairs<<<(NQUAD + 127) / 128, 128>>>();
    k_gate <<<Cc * Hh, Ll>>>(lg);
    k_intra_mma<<<dim3(16, Hh, Cc), 128, IN_SIZE>>>(q, k, v);
    k_state_mma<<<dim3(NSLOT / 128, Hh, Cc), 128>>>(k, v);
    k_scan <<<(Hh * NSLOT * NVP + 255) / 256, 256>>>();
    k_inter_mma<<<dim3(16, Hh, Cc), 128>>>(q, out);
}